// round 7
// baseline (speedup 1.0000x reference)
#include <cuda_runtime.h>

#define NTHR 512

// ---------------- shared memory layout (in floats) ----------------
#define WBT_SZ  (9*32*64)              // 18432 : wbT[a][i][o], o contiguous
#define WOT_SZ  (9*32*32)              //  9216 : woT[a][i][o]
#define XS_SZ   (32*68)                //  2176 : xs[i][k*4+t], row stride 68 (pad)
#define HS_SZ   (64*68)                //  4352 : hs[ch][k*4+t]
#define GS_SZ   (32*68)                //  2176 : gs[ch][k*4+t]
#define WBT_OFF 0
#define WOT_OFF (WBT_OFF + WBT_SZ)
#define XS_OFF  (WOT_OFF + WOT_SZ)
#define HS_OFF  (XS_OFF + XS_SZ)
#define GS_OFF  (HS_OFF + HS_SZ)
#define BB_OFF  (GS_OFF + GS_SZ)       // 64 floats
#define BO_OFF  (BB_OFF + 64)          // 32 floats
#define RW_OFF  (BO_OFF + 32)          // 4 floats
#define F_TOTAL (RW_OFF + 4)
#define I_TOTAL (256 + 256 + 16 + 16)  // gp terms, jc terms, counts
#define SMEM_BYTES ((F_TOTAL + I_TOTAL) * 4)

// ---------------- blade algebra constants ----------------
// blade order: 1,e0,e1,e2,e3,e01,e02,e03,e12,e13,e23,e012,e013,e023,e123,e0123
__constant__ int c_GRADE[16] = {0,1,1,1,1,2,2,2,2,2,2,3,3,3,3,4};
__constant__ int c_PART [16] = {-1,0,-1,-1,-1,2,3,4,-1,-1,-1,8,9,10,-1,14};
__constant__ int c_A2   [16] = {0,5,0,0,0,6,6,6,0,0,0,7,7,7,0,8};
__constant__ int c_EK[8]   = {1,5,6,7,11,12,13,15};   // e0-containing comps (64 MAC)
__constant__ int c_NK[8]   = {0,2,3,4,8,9,10,14};     // others (32 MAC)
__constant__ int c_KORD[16] = {1,5,6,7, 0,2,3,4, 11,12,13,15, 8,9,10,14}; // SMSP-balanced
__constant__ int c_MASK[16]  = {0,1,2,4,8,3,5,9,6,10,12,7,11,13,14,15};
__constant__ int c_IMASK[16] = {0,1,2,5,3,6,8,11,4,7,9,12,10,13,14,15};

__device__ __forceinline__ int inv_count(int A, int B) {
    int inv = 0;
    #pragma unroll
    for (int g = 0; g < 4; g++)
        if ((B >> g) & 1) inv += __popc(A >> (g + 1));
    return inv;
}

// equi_linear task: one (output channel o, component k), 4 tokens vectorized.
// wT: [a][i][co] with co contiguous (stride `co_stride` per i).
// xin rows: xin[i*68 + comp*4 + t].
__device__ __forceinline__ void equi_task(
    int k, int o, int co_stride, const float* __restrict__ wT,
    const float* __restrict__ xin, const float* __restrict__ bias,
    float* __restrict__ dst)
{
    float a0 = 0.f, a1 = 0.f, a2 = 0.f, a3 = 0.f;
    int g = c_GRADE[k];
    const float* w  = wT + (g * 32) * co_stride + o;
    const float* xc = xin + k * 4;
    #pragma unroll
    for (int i = 0; i < 32; i++) {
        float wv = w[i * co_stride];
        float4 xv = *(const float4*)(xc + i * 68);
        a0 = fmaf(wv, xv.x, a0); a1 = fmaf(wv, xv.y, a1);
        a2 = fmaf(wv, xv.z, a2); a3 = fmaf(wv, xv.w, a3);
    }
    int pk = c_PART[k];
    if (pk >= 0) {
        const float* w2 = wT + (c_A2[k] * 32) * co_stride + o;
        const float* x2 = xin + pk * 4;
        #pragma unroll
        for (int i = 0; i < 32; i++) {
            float wv = w2[i * co_stride];
            float4 xv = *(const float4*)(x2 + i * 68);
            a0 = fmaf(wv, xv.x, a0); a1 = fmaf(wv, xv.y, a1);
            a2 = fmaf(wv, xv.z, a2); a3 = fmaf(wv, xv.w, a3);
        }
    }
    if (k == 0) { float b = bias[o]; a0 += b; a1 += b; a2 += b; a3 += b; }
    *(float4*)(dst + o * 68 + k * 4) = make_float4(a0, a1, a2, a3);
}

__global__ __launch_bounds__(NTHR, 1)
void gatr_fused_kernel(
    const float* __restrict__ x, const float* __restrict__ ref,
    const float* __restrict__ w_bil, const float* __restrict__ b_bil,
    const float* __restrict__ w_out, const float* __restrict__ b_out,
    float* __restrict__ out, int ngroups)
{
    extern __shared__ float sm[];
    float* wbT = sm + WBT_OFF;
    float* woT = sm + WOT_OFF;
    float* xs  = sm + XS_OFF;   // also reused as output staging in P4/P5
    float* hs  = sm + HS_OFF;
    float* gs  = sm + GS_OFF;
    float* bb  = sm + BB_OFF;
    float* bo  = sm + BO_OFF;
    float* rw  = sm + RW_OFF;
    int* gp_t = (int*)(sm + F_TOTAL);
    int* jc_t = gp_t + 256;
    int* gp_n = jc_t + 256;
    int* jc_n = gp_n + 16;

    const int tid = threadIdx.x;

    // ---- stage weights transposed ----
    for (int e = tid; e < 64 * 32 * 9; e += NTHR) {
        int o = e / 288, r = e % 288, i = r / 9, a = r % 9;
        wbT[(a * 32 + i) * 64 + o] = w_bil[e];
    }
    for (int e = tid; e < 32 * 32 * 9; e += NTHR) {
        int o = e / 288, r = e % 288, i = r / 9, a = r % 9;
        woT[(a * 32 + i) * 32 + o] = w_out[e];
    }
    if (tid < 64) bb[tid] = b_bil[tid];
    if (tid < 32) bo[tid] = b_out[tid];

    // ---- build GP / JC term lists (deterministic, serial per table) ----
    if (tid == 0) {
        for (int k = 0; k < 16; k++) gp_n[k] = 0;
        for (int i = 0; i < 16; i++)
            for (int j = 0; j < 16; j++) {
                int A = c_MASK[i], B = c_MASK[j];
                if (A & B & 1) continue;                // e0*e0 = 0
                int s = inv_count(A, B) & 1;
                int k = c_IMASK[A ^ B];
                gp_t[k * 16 + gp_n[k]++] = i | (j << 5) | (s << 10);
            }
    }
    if (tid == 1) {
        int ds[16];
        for (int i = 0; i < 16; i++) {
            int A = c_MASK[i];
            ds[i] = (inv_count(A, 15 ^ A) & 1) ? -1 : 1;
        }
        for (int k = 0; k < 16; k++) jc_n[k] = 0;
        for (int i = 0; i < 16; i++)
            for (int j = 0; j < 16; j++) {
                int A = c_MASK[i], B = c_MASK[j];
                int da = 15 ^ A, db = 15 ^ B;
                if (da & db) continue;                  // wedge of duals vanishes
                int w = (inv_count(da, db) & 1) ? -1 : 1;
                int kk = c_IMASK[A & B];                // comp(da|db)
                int val = ds[i] * ds[j] * w * ds[kk];
                jc_t[kk * 16 + jc_n[kk]++] = i | (j << 5) | ((val < 0 ? 1 : 0) << 10);
            }
    }
    __syncthreads();

    for (int g = blockIdx.x; g < ngroups; g += gridDim.x) {
        // ---- P1: load 4 tokens of x into xs[i][k*4+t], and ref scalars ----
        {
            int t = tid >> 7, e = tid & 127;
            size_t tok = (size_t)g * 4 + t;
            float4 v = *(const float4*)(x + tok * 512 + (size_t)e * 4);
            float* b = xs + (e >> 2) * 68 + (e & 3) * 16 + t;
            b[0] = v.x; b[4] = v.y; b[8] = v.z; b[12] = v.w;
            if (tid < 4) rw[tid] = ref[((size_t)g * 4 + tid) * 16 + 15];
        }
        __syncthreads();

        // ---- P2: equi_linear #1 -> hs[64][16][4] (balanced E/N task split) ----
        {
            int q = tid >> 6, o = tid & 63;
            equi_task(c_EK[q], o, 64, wbT, xs, bb, hs);
            equi_task(c_NK[q], o, 64, wbT, xs, bb, hs);
        }
        __syncthreads();

        // ---- P3: geometric product + join -> gs[32][16][4] ----
        {
            int side = tid >> 8;          // 0 = GP, 1 = join
            int c    = (tid >> 4) & 15;
            int k    = tid & 15;
            const int* terms = (side ? jc_t : gp_t) + k * 16;
            int n            =  side ? jc_n[k]     : gp_n[k];
            const float* L = hs + (side * 32 + c) * 68;
            const float* R = hs + (side * 32 + 16 + c) * 68;
            float p0 = 0.f, p1 = 0.f, p2 = 0.f, p3 = 0.f;
            float q0 = 0.f, q1 = 0.f, q2 = 0.f, q3 = 0.f;
            for (int e = 0; e < n; e++) {
                int tm = terms[e];
                float4 av = *(const float4*)(L + (tm & 31) * 4);
                float4 bv = *(const float4*)(R + ((tm >> 5) & 31) * 4);
                if (tm & 1024) {
                    q0 = fmaf(av.x, bv.x, q0); q1 = fmaf(av.y, bv.y, q1);
                    q2 = fmaf(av.z, bv.z, q2); q3 = fmaf(av.w, bv.w, q3);
                } else {
                    p0 = fmaf(av.x, bv.x, p0); p1 = fmaf(av.y, bv.y, p1);
                    p2 = fmaf(av.z, bv.z, p2); p3 = fmaf(av.w, bv.w, p3);
                }
            }
            float r0 = p0 - q0, r1 = p1 - q1, r2 = p2 - q2, r3 = p3 - q3;
            if (side) { r0 *= rw[0]; r1 *= rw[1]; r2 *= rw[2]; r3 *= rw[3]; }
            *(float4*)(gs + (side * 16 + c) * 68 + k * 4) = make_float4(r0, r1, r2, r3);
        }
        __syncthreads();

        // ---- P4: equi_linear #2 -> staging in xs (reused) ----
        {
            int o = tid & 31;
            int k = c_KORD[tid >> 5];
            equi_task(k, o, 32, woT, gs, bo, xs);
        }
        __syncthreads();

        // ---- P5: coalesced store ----
        {
            int t = tid >> 7, e = tid & 127;
            size_t tok = (size_t)g * 4 + t;
            const float* b = xs + (e >> 2) * 68 + (e & 3) * 16 + t;
            float4 v = make_float4(b[0], b[4], b[8], b[12]);
            *(float4*)(out + tok * 512 + (size_t)e * 4) = v;
        }
        __syncthreads();
    }
}

extern "C" void kernel_launch(void* const* d_in, const int* in_sizes, int n_in,
                              void* d_out, int out_size)
{
    const float* x     = (const float*)d_in[0];
    const float* ref   = (const float*)d_in[1];
    const float* w_bil = (const float*)d_in[2];
    const float* b_bil = (const float*)d_in[3];
    const float* w_out = (const float*)d_in[4];
    const float* b_out = (const float*)d_in[5];
    float* out = (float*)d_out;

    int ntok    = in_sizes[0] / 512;   // 32 channels * 16 components
    int ngroups = ntok / 4;

    cudaFuncSetAttribute(gatr_fused_kernel,
                         cudaFuncAttributeMaxDynamicSharedMemorySize, SMEM_BYTES);
    gatr_fused_kernel<<<152, NTHR, SMEM_BYTES>>>(x, ref, w_bil, b_bil, w_out, b_out,
                                                 out, ngroups);
}

// round 8
// speedup vs baseline: 1.3578x; 1.3578x over previous
#include <cuda_runtime.h>

#define NTHR 512
#define TPG  8            // tokens per group
#define S    132          // staging row stride in floats (16 comps * 8 tok + 4 pad)

// ---------------- shared memory layout (in floats) ----------------
#define WBT_SZ  (9*32*64)              // wbT[a][i][o], o contiguous
#define WOT_SZ  (9*32*32)              // woT[a][i][o]
#define XS_SZ   (32*S)                 // xs[i][k*8+t]
#define HS_SZ   (64*S)                 // hs[ch][k*8+t]
#define GS_SZ   (32*S)                 // gs[ch][k*8+t]
#define WBT_OFF 0
#define WOT_OFF (WBT_OFF + WBT_SZ)
#define XS_OFF  (WOT_OFF + WOT_SZ)
#define HS_OFF  (XS_OFF + XS_SZ)
#define GS_OFF  (HS_OFF + HS_SZ)
#define BB_OFF  (GS_OFF + GS_SZ)       // 64 floats
#define BO_OFF  (BB_OFF + 64)          // 32 floats
#define RW_OFF  (BO_OFF + 32)          // 8 floats
#define F_TOTAL (RW_OFF + 8)
#define I_TOTAL (256 + 256 + 16 + 16)  // gp terms, jc terms, counts
#define SMEM_BYTES ((F_TOTAL + I_TOTAL) * 4)

// ---------------- blade algebra constants ----------------
// blade order: 1,e0,e1,e2,e3,e01,e02,e03,e12,e13,e23,e012,e013,e023,e123,e0123
__constant__ int c_GRADE[16] = {0,1,1,1,1,2,2,2,2,2,2,3,3,3,3,4};
__constant__ int c_PART [16] = {-1,0,-1,-1,-1,2,3,4,-1,-1,-1,8,9,10,-1,14};
__constant__ int c_A2   [16] = {0,5,0,0,0,6,6,6,0,0,0,7,7,7,0,8};
// warp->component map: groups of 4 EK warps / 4 NK warps so each SMSP gets 2+2
__constant__ int c_KORD[16] = {1,5,6,7, 0,2,3,4, 11,12,13,15, 8,9,10,14};
__constant__ int c_MASK[16]  = {0,1,2,4,8,3,5,9,6,10,12,7,11,13,14,15};
__constant__ int c_IMASK[16] = {0,1,2,5,3,6,8,11,4,7,9,12,10,13,14,15};

__device__ __forceinline__ int inv_count(int A, int B) {
    int inv = 0;
    #pragma unroll
    for (int g = 0; g < 4; g++)
        if ((B >> g) & 1) inv += __popc(A >> (g + 1));
    return inv;
}

// equi_linear task: (component k, output-channel pair o0/o0+1), 8 tokens.
// wT: [a][i][co] with co contiguous (row stride cs). xin rows: xin[i*S + comp*8 + t].
__device__ __forceinline__ void equi_task2(
    int k, int o0, int cs, const float* __restrict__ wT,
    const float* __restrict__ xin, const float* __restrict__ bias,
    float* __restrict__ dst)
{
    float aA[8], aB[8];
    #pragma unroll
    for (int j = 0; j < 8; j++) { aA[j] = 0.f; aB[j] = 0.f; }

    int g = c_GRADE[k];
    const float* w  = wT + (g * 32) * cs + o0;
    const float* xc = xin + k * 8;
    #pragma unroll
    for (int i = 0; i < 32; i++) {
        float2 wv = *(const float2*)(w + i * cs);
        float4 x0 = *(const float4*)(xc + i * S);
        float4 x1 = *(const float4*)(xc + i * S + 4);
        aA[0]=fmaf(wv.x,x0.x,aA[0]); aA[1]=fmaf(wv.x,x0.y,aA[1]);
        aA[2]=fmaf(wv.x,x0.z,aA[2]); aA[3]=fmaf(wv.x,x0.w,aA[3]);
        aA[4]=fmaf(wv.x,x1.x,aA[4]); aA[5]=fmaf(wv.x,x1.y,aA[5]);
        aA[6]=fmaf(wv.x,x1.z,aA[6]); aA[7]=fmaf(wv.x,x1.w,aA[7]);
        aB[0]=fmaf(wv.y,x0.x,aB[0]); aB[1]=fmaf(wv.y,x0.y,aB[1]);
        aB[2]=fmaf(wv.y,x0.z,aB[2]); aB[3]=fmaf(wv.y,x0.w,aB[3]);
        aB[4]=fmaf(wv.y,x1.x,aB[4]); aB[5]=fmaf(wv.y,x1.y,aB[5]);
        aB[6]=fmaf(wv.y,x1.z,aB[6]); aB[7]=fmaf(wv.y,x1.w,aB[7]);
    }
    int pk = c_PART[k];
    if (pk >= 0) {
        const float* w2 = wT + (c_A2[k] * 32) * cs + o0;
        const float* x2 = xin + pk * 8;
        #pragma unroll
        for (int i = 0; i < 32; i++) {
            float2 wv = *(const float2*)(w2 + i * cs);
            float4 x0 = *(const float4*)(x2 + i * S);
            float4 x1 = *(const float4*)(x2 + i * S + 4);
            aA[0]=fmaf(wv.x,x0.x,aA[0]); aA[1]=fmaf(wv.x,x0.y,aA[1]);
            aA[2]=fmaf(wv.x,x0.z,aA[2]); aA[3]=fmaf(wv.x,x0.w,aA[3]);
            aA[4]=fmaf(wv.x,x1.x,aA[4]); aA[5]=fmaf(wv.x,x1.y,aA[5]);
            aA[6]=fmaf(wv.x,x1.z,aA[6]); aA[7]=fmaf(wv.x,x1.w,aA[7]);
            aB[0]=fmaf(wv.y,x0.x,aB[0]); aB[1]=fmaf(wv.y,x0.y,aB[1]);
            aB[2]=fmaf(wv.y,x0.z,aB[2]); aB[3]=fmaf(wv.y,x0.w,aB[3]);
            aB[4]=fmaf(wv.y,x1.x,aB[4]); aB[5]=fmaf(wv.y,x1.y,aB[5]);
            aB[6]=fmaf(wv.y,x1.z,aB[6]); aB[7]=fmaf(wv.y,x1.w,aB[7]);
        }
    }
    if (k == 0) {
        float bA = bias[o0], bB = bias[o0 + 1];
        #pragma unroll
        for (int j = 0; j < 8; j++) { aA[j] += bA; aB[j] += bB; }
    }
    float* dA = dst + o0 * S + k * 8;
    float* dB = dA + S;
    *(float4*)(dA)     = make_float4(aA[0], aA[1], aA[2], aA[3]);
    *(float4*)(dA + 4) = make_float4(aA[4], aA[5], aA[6], aA[7]);
    *(float4*)(dB)     = make_float4(aB[0], aB[1], aB[2], aB[3]);
    *(float4*)(dB + 4) = make_float4(aB[4], aB[5], aB[6], aB[7]);
}

// equi_linear task for P4: (k, o-pair, token-half th), 4 tokens.
__device__ __forceinline__ void equi_task2h(
    int k, int o0, int th, const float* __restrict__ wT,
    const float* __restrict__ xin, const float* __restrict__ bias,
    float* __restrict__ dst)
{
    float aA[4], aB[4];
    #pragma unroll
    for (int j = 0; j < 4; j++) { aA[j] = 0.f; aB[j] = 0.f; }

    int g = c_GRADE[k];
    const float* w  = wT + (g * 32) * 32 + o0;
    const float* xc = xin + k * 8 + th * 4;
    #pragma unroll
    for (int i = 0; i < 32; i++) {
        float2 wv = *(const float2*)(w + i * 32);
        float4 xv = *(const float4*)(xc + i * S);
        aA[0]=fmaf(wv.x,xv.x,aA[0]); aA[1]=fmaf(wv.x,xv.y,aA[1]);
        aA[2]=fmaf(wv.x,xv.z,aA[2]); aA[3]=fmaf(wv.x,xv.w,aA[3]);
        aB[0]=fmaf(wv.y,xv.x,aB[0]); aB[1]=fmaf(wv.y,xv.y,aB[1]);
        aB[2]=fmaf(wv.y,xv.z,aB[2]); aB[3]=fmaf(wv.y,xv.w,aB[3]);
    }
    int pk = c_PART[k];
    if (pk >= 0) {
        const float* w2 = wT + (c_A2[k] * 32) * 32 + o0;
        const float* x2 = xin + pk * 8 + th * 4;
        #pragma unroll
        for (int i = 0; i < 32; i++) {
            float2 wv = *(const float2*)(w2 + i * 32);
            float4 xv = *(const float4*)(x2 + i * S);
            aA[0]=fmaf(wv.x,xv.x,aA[0]); aA[1]=fmaf(wv.x,xv.y,aA[1]);
            aA[2]=fmaf(wv.x,xv.z,aA[2]); aA[3]=fmaf(wv.x,xv.w,aA[3]);
            aB[0]=fmaf(wv.y,xv.x,aB[0]); aB[1]=fmaf(wv.y,xv.y,aB[1]);
            aB[2]=fmaf(wv.y,xv.z,aB[2]); aB[3]=fmaf(wv.y,xv.w,aB[3]);
        }
    }
    if (k == 0) {
        float bA = bias[o0], bB = bias[o0 + 1];
        #pragma unroll
        for (int j = 0; j < 4; j++) { aA[j] += bA; aB[j] += bB; }
    }
    float* dA = dst + o0 * S + k * 8 + th * 4;
    *(float4*)(dA)     = make_float4(aA[0], aA[1], aA[2], aA[3]);
    *(float4*)(dA + S) = make_float4(aB[0], aB[1], aB[2], aB[3]);
}

__global__ __launch_bounds__(NTHR, 1)
void gatr_fused_kernel(
    const float* __restrict__ x, const float* __restrict__ ref,
    const float* __restrict__ w_bil, const float* __restrict__ b_bil,
    const float* __restrict__ w_out, const float* __restrict__ b_out,
    float* __restrict__ out, int ngroups)
{
    extern __shared__ float sm[];
    float* wbT = sm + WBT_OFF;
    float* woT = sm + WOT_OFF;
    float* xs  = sm + XS_OFF;   // reused as output staging in P4/P5
    float* hs  = sm + HS_OFF;
    float* gs  = sm + GS_OFF;
    float* bb  = sm + BB_OFF;
    float* bo  = sm + BO_OFF;
    float* rw  = sm + RW_OFF;
    int* gp_t = (int*)(sm + F_TOTAL);
    int* jc_t = gp_t + 256;
    int* gp_n = jc_t + 256;
    int* jc_n = gp_n + 16;

    const int tid = threadIdx.x;

    // ---- stage weights transposed ----
    for (int e = tid; e < 64 * 32 * 9; e += NTHR) {
        int o = e / 288, r = e % 288, i = r / 9, a = r % 9;
        wbT[(a * 32 + i) * 64 + o] = w_bil[e];
    }
    for (int e = tid; e < 32 * 32 * 9; e += NTHR) {
        int o = e / 288, r = e % 288, i = r / 9, a = r % 9;
        woT[(a * 32 + i) * 32 + o] = w_out[e];
    }
    if (tid < 64) bb[tid] = b_bil[tid];
    if (tid < 32) bo[tid] = b_out[tid];

    // ---- build GP / JC term lists (deterministic, serial per table) ----
    if (tid == 0) {
        for (int k = 0; k < 16; k++) gp_n[k] = 0;
        for (int i = 0; i < 16; i++)
            for (int j = 0; j < 16; j++) {
                int A = c_MASK[i], B = c_MASK[j];
                if (A & B & 1) continue;                // e0*e0 = 0
                int s = inv_count(A, B) & 1;
                int k = c_IMASK[A ^ B];
                gp_t[k * 16 + gp_n[k]++] = i | (j << 5) | (s << 10);
            }
    }
    if (tid == 1) {
        int ds[16];
        for (int i = 0; i < 16; i++) {
            int A = c_MASK[i];
            ds[i] = (inv_count(A, 15 ^ A) & 1) ? -1 : 1;
        }
        for (int k = 0; k < 16; k++) jc_n[k] = 0;
        for (int i = 0; i < 16; i++)
            for (int j = 0; j < 16; j++) {
                int A = c_MASK[i], B = c_MASK[j];
                int da = 15 ^ A, db = 15 ^ B;
                if (da & db) continue;                  // wedge of duals vanishes
                int w = (inv_count(da, db) & 1) ? -1 : 1;
                int kk = c_IMASK[A & B];                // comp(da|db)
                int val = ds[i] * ds[j] * w * ds[kk];
                jc_t[kk * 16 + jc_n[kk]++] = i | (j << 5) | ((val < 0 ? 1 : 0) << 10);
            }
    }
    __syncthreads();

    for (int g = blockIdx.x; g < ngroups; g += gridDim.x) {
        // ---- P1: load 8 tokens of x into xs[i][k*8+t], and ref scalars ----
        {
            #pragma unroll
            for (int it = 0; it < 2; it++) {
                int idx = tid + it * NTHR;
                int t = idx >> 7, e = idx & 127;
                size_t tok = (size_t)g * TPG + t;
                float4 v = *(const float4*)(x + tok * 512 + (size_t)e * 4);
                float* b = xs + (e >> 2) * S + (e & 3) * 32 + t;
                b[0] = v.x; b[8] = v.y; b[16] = v.z; b[24] = v.w;
            }
            if (tid < TPG) rw[tid] = ref[((size_t)g * TPG + tid) * 16 + 15];
        }
        __syncthreads();

        // ---- P2: equi_linear #1 -> hs[64][16][8] (k uniform per warp) ----
        {
            int w = tid >> 5, op = tid & 31;
            equi_task2(c_KORD[w], op * 2, 64, wbT, xs, bb, hs);
        }
        __syncthreads();

        // ---- P3: geometric product + join -> gs[32][16][8] ----
        {
            int side = tid >> 8;          // 0 = GP, 1 = join
            int c    = (tid >> 4) & 15;
            int k    = tid & 15;
            const int* terms = (side ? jc_t : gp_t) + k * 16;
            int n            =  side ? jc_n[k]     : gp_n[k];
            const float* L = hs + (side * 32 + c) * S;
            const float* R = hs + (side * 32 + 16 + c) * S;
            float p[8], q[8];
            #pragma unroll
            for (int j = 0; j < 8; j++) { p[j] = 0.f; q[j] = 0.f; }
            for (int e = 0; e < n; e++) {
                int tm = terms[e];
                const float* la = L + (tm & 31) * 8;
                const float* rb = R + ((tm >> 5) & 31) * 8;
                float4 a0 = *(const float4*)(la);
                float4 a1 = *(const float4*)(la + 4);
                float4 b0 = *(const float4*)(rb);
                float4 b1 = *(const float4*)(rb + 4);
                if (tm & 1024) {
                    q[0]=fmaf(a0.x,b0.x,q[0]); q[1]=fmaf(a0.y,b0.y,q[1]);
                    q[2]=fmaf(a0.z,b0.z,q[2]); q[3]=fmaf(a0.w,b0.w,q[3]);
                    q[4]=fmaf(a1.x,b1.x,q[4]); q[5]=fmaf(a1.y,b1.y,q[5]);
                    q[6]=fmaf(a1.z,b1.z,q[6]); q[7]=fmaf(a1.w,b1.w,q[7]);
                } else {
                    p[0]=fmaf(a0.x,b0.x,p[0]); p[1]=fmaf(a0.y,b0.y,p[1]);
                    p[2]=fmaf(a0.z,b0.z,p[2]); p[3]=fmaf(a0.w,b0.w,p[3]);
                    p[4]=fmaf(a1.x,b1.x,p[4]); p[5]=fmaf(a1.y,b1.y,p[5]);
                    p[6]=fmaf(a1.z,b1.z,p[6]); p[7]=fmaf(a1.w,b1.w,p[7]);
                }
            }
            float r[8];
            #pragma unroll
            for (int j = 0; j < 8; j++) r[j] = p[j] - q[j];
            if (side) {
                #pragma unroll
                for (int j = 0; j < 8; j++) r[j] *= rw[j];
            }
            float* d = gs + (side * 16 + c) * S + k * 8;
            *(float4*)(d)     = make_float4(r[0], r[1], r[2], r[3]);
            *(float4*)(d + 4) = make_float4(r[4], r[5], r[6], r[7]);
        }
        __syncthreads();

        // ---- P4: equi_linear #2 -> staging in xs (reused) ----
        {
            int w = tid >> 5, lane = tid & 31;
            int op = lane >> 1, th = lane & 1;
            equi_task2h(c_KORD[w], op * 2, th, woT, gs, bo, xs);
        }
        __syncthreads();

        // ---- P5: coalesced store ----
        {
            #pragma unroll
            for (int it = 0; it < 2; it++) {
                int idx = tid + it * NTHR;
                int t = idx >> 7, e = idx & 127;
                size_t tok = (size_t)g * TPG + t;
                const float* b = xs + (e >> 2) * S + (e & 3) * 32 + t;
                float4 v = make_float4(b[0], b[8], b[16], b[24]);
                *(float4*)(out + tok * 512 + (size_t)e * 4) = v;
            }
        }
        __syncthreads();
    }
}

extern "C" void kernel_launch(void* const* d_in, const int* in_sizes, int n_in,
                              void* d_out, int out_size)
{
    const float* x     = (const float*)d_in[0];
    const float* ref   = (const float*)d_in[1];
    const float* w_bil = (const float*)d_in[2];
    const float* b_bil = (const float*)d_in[3];
    const float* w_out = (const float*)d_in[4];
    const float* b_out = (const float*)d_in[5];
    float* out = (float*)d_out;

    int ntok    = in_sizes[0] / 512;   // 32 channels * 16 components
    int ngroups = ntok / TPG;

    cudaFuncSetAttribute(gatr_fused_kernel,
                         cudaFuncAttributeMaxDynamicSharedMemorySize, SMEM_BYTES);
    gatr_fused_kernel<<<152, NTHR, SMEM_BYTES>>>(x, ref, w_bil, b_bil, w_out, b_out,
                                                 out, ngroups);
}

// round 9
// speedup vs baseline: 2.7260x; 2.0078x over previous
#include <cuda_runtime.h>

#define NTHR 512
#define TPG  16            // tokens per group
#define S    276           // row stride in floats (16*16 + 20 pad)

typedef unsigned long long ull;

// ---------------- shared memory layout (in floats) ----------------
#define WBT_SZ  (9*32*64)              // wbT[a][i][o], o contiguous
#define WOT_SZ  (9*32*32)              // woT[a][i][o]
#define XS_SZ   (32*S + 8)             // xs rows (aliased by gs)
#define HS_SZ   (64*S + 8)             // hs rows (aliased by out-staging)
#define WBT_OFF 0
#define WOT_OFF (WBT_OFF + WBT_SZ)
#define XS_OFF  (WOT_OFF + WOT_SZ)
#define HS_OFF  (XS_OFF + XS_SZ)
#define BB_OFF  (HS_OFF + HS_SZ)       // 64
#define BO_OFF  (BB_OFF + 64)          // 32
#define RW_OFF  (BO_OFF + 32)          // 16
#define F_TOTAL (RW_OFF + 16)
#define SMEM_BYTES (F_TOTAL * 4)

// component slot swizzle (bijective), and bank-swizzled row offsets
__host__ __device__ constexpr int cslot(int k) { return k ^ (k >> 2); }
__host__ __device__ constexpr int rowX(int i)  { return XS_OFF + i * S + ((i >> 3) & 1) * 4; }
__host__ __device__ constexpr int rowH(int o)  { return HS_OFF + o * S + ((o >> 3) & 1) * 4; }

// ---------------- blade algebra ----------------
// blade order: 1,e0,e1,e2,e3,e01,e02,e03,e12,e13,e23,e012,e013,e023,e123,e0123
__constant__ int c_GRADE[16] = {0,1,1,1,1,2,2,2,2,2,2,3,3,3,3,4};
__constant__ int c_PART [16] = {-1,0,-1,-1,-1,2,3,4,-1,-1,-1,8,9,10,-1,14};
__constant__ int c_A2   [16] = {0,5,0,0,0,6,6,6,0,0,0,7,7,7,0,8};
__constant__ int c_KORD [16] = {1,5,6,7, 0,2,3,4, 11,12,13,15, 8,9,10,14}; // SMSP-balanced

// ---- compile-time Cayley tables ----
constexpr int MASKC[16]  = {0,1,2,4,8,3,5,9,6,10,12,7,11,13,14,15};
constexpr int IMASKC[16] = {0,1,2,5,3,6,8,11,4,7,9,12,10,13,14,15};
constexpr int popc4c(int x) { int v = 0; for (int b = 0; b < 4; b++) v += (x >> b) & 1; return v; }
constexpr int invcc(int A, int B) {
    int v = 0;
    for (int g = 0; g < 4; g++) if ((B >> g) & 1) v += popc4c(A >> (g + 1));
    return v;
}
struct CTerm { int i, j, s; };
struct CK    { CTerm t[16]; int n; };
struct CTabs { CK gp[16]; CK jc[16]; };
constexpr CTabs buildT() {
    CTabs T{};
    for (int i = 0; i < 16; i++)
        for (int j = 0; j < 16; j++) {
            int A = MASKC[i], B = MASKC[j];
            if (A & B & 1) continue;                    // e0*e0 = 0
            int s = (invcc(A, B) & 1) ? -1 : 1;
            int k = IMASKC[A ^ B];
            T.gp[k].t[T.gp[k].n].i = i;
            T.gp[k].t[T.gp[k].n].j = j;
            T.gp[k].t[T.gp[k].n].s = s;
            T.gp[k].n++;
        }
    int ds[16] = {};
    for (int i = 0; i < 16; i++) {
        int A = MASKC[i];
        ds[i] = (invcc(A, 15 ^ A) & 1) ? -1 : 1;
    }
    for (int i = 0; i < 16; i++)
        for (int j = 0; j < 16; j++) {
            int A = MASKC[i], B = MASKC[j];
            int da = 15 ^ A, db = 15 ^ B;
            if (da & db) continue;                      // wedge of duals vanishes
            int w  = (invcc(da, db) & 1) ? -1 : 1;
            int kk = IMASKC[A & B];
            int val = ds[i] * ds[j] * w * ds[kk];
            T.jc[kk].t[T.jc[kk].n].i = i;
            T.jc[kk].t[T.jc[kk].n].j = j;
            T.jc[kk].t[T.jc[kk].n].s = val;
            T.jc[kk].n++;
        }
    return T;
}
constexpr CTabs CT = buildT();

// ---- packed f32x2 helpers ----
__device__ __forceinline__ void fma2(ull& d, ull a, ull b) {
    asm("fma.rn.f32x2 %0, %1, %2, %0;" : "+l"(d) : "l"(a), "l"(b));
}
__device__ __forceinline__ ull pk2(float s) {
    ull d; asm("mov.b64 %0, {%1, %1};" : "=l"(d) : "f"(s)); return d;
}
__device__ __forceinline__ void add2(ull& d, ull a) {
    asm("add.rn.f32x2 %0, %0, %1;" : "+l"(d) : "l"(a));
}

// ---- equi_linear, 16 tokens, o-pair, packed ----
__device__ __forceinline__ void el16(
    int k, int o0, int cs, const float* __restrict__ wT,
    const float* __restrict__ sm, const float* __restrict__ bias,
    float* __restrict__ smw)
{
    ull aA[8], aB[8];
    #pragma unroll
    for (int q = 0; q < 8; q++) { aA[q] = 0ull; aB[q] = 0ull; }

    int g  = c_GRADE[k];
    int sl = cslot(k) * 16;
    {
        const float* w = wT + (g * 32) * cs + o0;
        #pragma unroll
        for (int i = 0; i < 32; i++) {
            float2 wv = *(const float2*)(w + i * cs);
            ull w2a = pk2(wv.x), w2b = pk2(wv.y);
            const float* xp = sm + rowX(i) + sl;
            ulonglong2 x0 = *(const ulonglong2*)(xp);
            ulonglong2 x1 = *(const ulonglong2*)(xp + 4);
            ulonglong2 x2 = *(const ulonglong2*)(xp + 8);
            ulonglong2 x3 = *(const ulonglong2*)(xp + 12);
            fma2(aA[0], x0.x, w2a); fma2(aA[1], x0.y, w2a);
            fma2(aA[2], x1.x, w2a); fma2(aA[3], x1.y, w2a);
            fma2(aA[4], x2.x, w2a); fma2(aA[5], x2.y, w2a);
            fma2(aA[6], x3.x, w2a); fma2(aA[7], x3.y, w2a);
            fma2(aB[0], x0.x, w2b); fma2(aB[1], x0.y, w2b);
            fma2(aB[2], x1.x, w2b); fma2(aB[3], x1.y, w2b);
            fma2(aB[4], x2.x, w2b); fma2(aB[5], x2.y, w2b);
            fma2(aB[6], x3.x, w2b); fma2(aB[7], x3.y, w2b);
        }
    }
    int pk = c_PART[k];
    if (pk >= 0) {
        int sl2 = cslot(pk) * 16;
        const float* w = wT + (c_A2[k] * 32) * cs + o0;
        #pragma unroll
        for (int i = 0; i < 32; i++) {
            float2 wv = *(const float2*)(w + i * cs);
            ull w2a = pk2(wv.x), w2b = pk2(wv.y);
            const float* xp = sm + rowX(i) + sl2;
            ulonglong2 x0 = *(const ulonglong2*)(xp);
            ulonglong2 x1 = *(const ulonglong2*)(xp + 4);
            ulonglong2 x2 = *(const ulonglong2*)(xp + 8);
            ulonglong2 x3 = *(const ulonglong2*)(xp + 12);
            fma2(aA[0], x0.x, w2a); fma2(aA[1], x0.y, w2a);
            fma2(aA[2], x1.x, w2a); fma2(aA[3], x1.y, w2a);
            fma2(aA[4], x2.x, w2a); fma2(aA[5], x2.y, w2a);
            fma2(aA[6], x3.x, w2a); fma2(aA[7], x3.y, w2a);
            fma2(aB[0], x0.x, w2b); fma2(aB[1], x0.y, w2b);
            fma2(aB[2], x1.x, w2b); fma2(aB[3], x1.y, w2b);
            fma2(aB[4], x2.x, w2b); fma2(aB[5], x2.y, w2b);
            fma2(aB[6], x3.x, w2b); fma2(aB[7], x3.y, w2b);
        }
    }
    if (k == 0) {
        ull bA = pk2(bias[o0]), bB = pk2(bias[o0 + 1]);
        #pragma unroll
        for (int q = 0; q < 8; q++) { add2(aA[q], bA); add2(aB[q], bB); }
    }
    float* dA = smw + sl;   // caller passes row base via smw? no: see below
    // store: rows passed via smw base (= sm + rowH(o0) ... handled by caller offsets)
    (void)dA;
    {
        float* pA = smw;            // sm + rowH(o0) + sl precomputed by caller
        float* pB = smw + (rowH(o0 + 1) - rowH(o0));
        *(ulonglong2*)(pA)      = make_ulonglong2(aA[0], aA[1]);
        *(ulonglong2*)(pA + 4)  = make_ulonglong2(aA[2], aA[3]);
        *(ulonglong2*)(pA + 8)  = make_ulonglong2(aA[4], aA[5]);
        *(ulonglong2*)(pA + 12) = make_ulonglong2(aA[6], aA[7]);
        *(ulonglong2*)(pB)      = make_ulonglong2(aB[0], aB[1]);
        *(ulonglong2*)(pB + 4)  = make_ulonglong2(aB[2], aB[3]);
        *(ulonglong2*)(pB + 8)  = make_ulonglong2(aB[4], aB[5]);
        *(ulonglong2*)(pB + 12) = make_ulonglong2(aB[6], aB[7]);
    }
}

// ---- equi_linear #2, 8 tokens (half), o-pair, packed; reads gs rows (xs region) ----
__device__ __forceinline__ void el8(
    int k, int o0, int th, const float* __restrict__ wT,
    const float* __restrict__ sm, const float* __restrict__ bias,
    float* __restrict__ smbase)
{
    ull aA[4], aB[4];
    #pragma unroll
    for (int q = 0; q < 4; q++) { aA[q] = 0ull; aB[q] = 0ull; }

    int g  = c_GRADE[k];
    int sl = cslot(k) * 16 + th * 8;
    {
        const float* w = wT + (g * 32) * 32 + o0;
        #pragma unroll
        for (int i = 0; i < 32; i++) {
            float2 wv = *(const float2*)(w + i * 32);
            ull w2a = pk2(wv.x), w2b = pk2(wv.y);
            const float* xp = sm + rowX(i) + sl;
            ulonglong2 x0 = *(const ulonglong2*)(xp);
            ulonglong2 x1 = *(const ulonglong2*)(xp + 4);
            fma2(aA[0], x0.x, w2a); fma2(aA[1], x0.y, w2a);
            fma2(aA[2], x1.x, w2a); fma2(aA[3], x1.y, w2a);
            fma2(aB[0], x0.x, w2b); fma2(aB[1], x0.y, w2b);
            fma2(aB[2], x1.x, w2b); fma2(aB[3], x1.y, w2b);
        }
    }
    int pk = c_PART[k];
    if (pk >= 0) {
        int sl2 = cslot(pk) * 16 + th * 8;
        const float* w = wT + (c_A2[k] * 32) * 32 + o0;
        #pragma unroll
        for (int i = 0; i < 32; i++) {
            float2 wv = *(const float2*)(w + i * 32);
            ull w2a = pk2(wv.x), w2b = pk2(wv.y);
            const float* xp = sm + rowX(i) + sl2;
            ulonglong2 x0 = *(const ulonglong2*)(xp);
            ulonglong2 x1 = *(const ulonglong2*)(xp + 4);
            fma2(aA[0], x0.x, w2a); fma2(aA[1], x0.y, w2a);
            fma2(aA[2], x1.x, w2a); fma2(aA[3], x1.y, w2a);
            fma2(aB[0], x0.x, w2b); fma2(aB[1], x0.y, w2b);
            fma2(aB[2], x1.x, w2b); fma2(aB[3], x1.y, w2b);
        }
    }
    if (k == 0) {
        ull bA = pk2(bias[o0]), bB = pk2(bias[o0 + 1]);
        #pragma unroll
        for (int q = 0; q < 4; q++) { add2(aA[q], bA); add2(aB[q], bB); }
    }
    float* pA = smbase + rowH(o0) + sl;
    float* pB = smbase + rowH(o0 + 1) + sl;
    *(ulonglong2*)(pA)     = make_ulonglong2(aA[0], aA[1]);
    *(ulonglong2*)(pA + 4) = make_ulonglong2(aA[2], aA[3]);
    *(ulonglong2*)(pB)     = make_ulonglong2(aB[0], aB[1]);
    *(ulonglong2*)(pB + 4) = make_ulonglong2(aB[2], aB[3]);
}

// ---- P3: one component K, compile-time term list ----
template<int SIDE, int K>
__device__ __forceinline__ float bil_k(const float (&L)[16], const float (&R)[16]) {
    constexpr CK ck = SIDE ? CT.jc[K] : CT.gp[K];
    float acc = 0.f;
    #pragma unroll
    for (int e = 0; e < ck.n; e++) {
        float l = (ck.t[e].s < 0) ? -L[ck.t[e].i] : L[ck.t[e].i];
        acc = fmaf(l, R[ck.t[e].j], acc);
    }
    return acc;
}

template<int SIDE, int K>
__device__ __forceinline__ void bil_all(const float (&L)[16], const float (&R)[16],
                                        float* __restrict__ dst, float scale) {
    if constexpr (K < 16) {
        float v = bil_k<SIDE, K>(L, R);
        if constexpr (SIDE) v *= scale;
        dst[cslot(K) * 16] = v;
        bil_all<SIDE, K + 1>(L, R, dst, scale);
    }
}

__global__ __launch_bounds__(NTHR, 1)
void gatr_fused_kernel(
    const float* __restrict__ x, const float* __restrict__ ref,
    const float* __restrict__ w_bil, const float* __restrict__ b_bil,
    const float* __restrict__ w_out, const float* __restrict__ b_out,
    float* __restrict__ out, int ngroups)
{
    extern __shared__ float sm[];
    float* wbT = sm + WBT_OFF;
    float* woT = sm + WOT_OFF;
    float* bb  = sm + BB_OFF;
    float* bo  = sm + BO_OFF;
    float* rw  = sm + RW_OFF;

    const int tid = threadIdx.x;

    // ---- stage weights transposed ----
    for (int e = tid; e < 64 * 32 * 9; e += NTHR) {
        int o = e / 288, r = e % 288, i = r / 9, a = r % 9;
        wbT[(a * 32 + i) * 64 + o] = w_bil[e];
    }
    for (int e = tid; e < 32 * 32 * 9; e += NTHR) {
        int o = e / 288, r = e % 288, i = r / 9, a = r % 9;
        woT[(a * 32 + i) * 32 + o] = w_out[e];
    }
    if (tid < 64) bb[tid] = b_bil[tid];
    if (tid < 32) bo[tid] = b_out[tid];

    const int e_id = tid & 127;
    const int t0   = (tid >> 7) * 4;

    // ---- prefetch + stage first group ----
    float4 pf[4];
    float  prw = 0.f;
    {
        int g = blockIdx.x;
        size_t base = ((size_t)g * TPG + t0) * 512 + (size_t)e_id * 4;
        #pragma unroll
        for (int j = 0; j < 4; j++) pf[j] = *(const float4*)(x + base + (size_t)j * 512);
        if (tid < TPG) prw = ref[((size_t)g * TPG + tid) * 16 + 15];
    }
    {
        const float* p0 = (const float*)&pf[0];
        const float* p1 = (const float*)&pf[1];
        const float* p2 = (const float*)&pf[2];
        const float* p3 = (const float*)&pf[3];
        #pragma unroll
        for (int c = 0; c < 4; c++) {
            int k = (e_id & 3) * 4 + c;
            float* d = sm + rowX(e_id >> 2) + cslot(k) * 16 + t0;
            *(float4*)d = make_float4(p0[c], p1[c], p2[c], p3[c]);
        }
        if (tid < TPG) rw[tid] = prw;
    }

    for (int g = blockIdx.x; g < ngroups; g += gridDim.x) {
        __syncthreads();   // xs / rw ready

        // prefetch next group (LDG latency hidden under P2)
        int gn = g + gridDim.x;
        bool more = gn < ngroups;
        if (more) {
            size_t base = ((size_t)gn * TPG + t0) * 512 + (size_t)e_id * 4;
            #pragma unroll
            for (int j = 0; j < 4; j++) pf[j] = *(const float4*)(x + base + (size_t)j * 512);
            if (tid < TPG) prw = ref[((size_t)gn * TPG + tid) * 16 + 15];
        }

        // ---- P2: equi_linear #1 -> hs rows 0..63 ----
        {
            int w = tid >> 5, op = tid & 31;
            int k = c_KORD[w], o0 = 2 * op;
            el16(k, o0, 64, wbT, sm, bb, sm + rowH(o0) + cslot(k) * 16);
        }
        __syncthreads();

        // ---- P3: GP + join -> gs (xs region) rows 0..31 ----
        {
            int side = tid >> 8, c = (tid >> 4) & 15, t = tid & 15;
            const float* Lp = sm + rowH(side * 32 + c) + t;
            const float* Rp = sm + rowH(side * 32 + 16 + c) + t;
            float L[16], R[16];
            #pragma unroll
            for (int i = 0; i < 16; i++) {
                L[i] = Lp[cslot(i) * 16];
                R[i] = Rp[cslot(i) * 16];
            }
            float* dst = sm + rowX(side * 16 + c) + t;
            float scale = rw[t];
            if (side == 0) bil_all<0, 0>(L, R, dst, scale);
            else           bil_all<1, 0>(L, R, dst, scale);
        }
        __syncthreads();

        // ---- P4: equi_linear #2 -> staging in hs region rows 0..31 ----
        {
            int w = tid >> 5, lane = tid & 31;
            int op = lane >> 1, th = lane & 1;
            el8(c_KORD[w], 2 * op, th, woT, sm, bo, sm);
        }
        __syncthreads();

        // ---- P5: coalesced store ----
        {
            float4 sv[4];
            #pragma unroll
            for (int c = 0; c < 4; c++) {
                int k = (e_id & 3) * 4 + c;
                sv[c] = *(const float4*)(sm + rowH(e_id >> 2) + cslot(k) * 16 + t0);
            }
            size_t base = ((size_t)g * TPG + t0) * 512 + (size_t)e_id * 4;
            const float* s0 = (const float*)&sv[0];
            const float* s1 = (const float*)&sv[1];
            const float* s2 = (const float*)&sv[2];
            const float* s3 = (const float*)&sv[3];
            #pragma unroll
            for (int j = 0; j < 4; j++)
                *(float4*)(out + base + (size_t)j * 512) =
                    make_float4(s0[j], s1[j], s2[j], s3[j]);
        }

        // ---- P1 for next group: stage prefetched regs into xs ----
        if (more) {
            const float* p0 = (const float*)&pf[0];
            const float* p1 = (const float*)&pf[1];
            const float* p2 = (const float*)&pf[2];
            const float* p3 = (const float*)&pf[3];
            #pragma unroll
            for (int c = 0; c < 4; c++) {
                int k = (e_id & 3) * 4 + c;
                float* d = sm + rowX(e_id >> 2) + cslot(k) * 16 + t0;
                *(float4*)d = make_float4(p0[c], p1[c], p2[c], p3[c]);
            }
            if (tid < TPG) rw[tid] = prw;
        }
    }
}

extern "C" void kernel_launch(void* const* d_in, const int* in_sizes, int n_in,
                              void* d_out, int out_size)
{
    const float* x     = (const float*)d_in[0];
    const float* ref   = (const float*)d_in[1];
    const float* w_bil = (const float*)d_in[2];
    const float* b_bil = (const float*)d_in[3];
    const float* w_out = (const float*)d_in[4];
    const float* b_out = (const float*)d_in[5];
    float* out = (float*)d_out;

    int ntok    = in_sizes[0] / 512;   // 32 channels * 16 components
    int ngroups = ntok / TPG;

    cudaFuncSetAttribute(gatr_fused_kernel,
                         cudaFuncAttributeMaxDynamicSharedMemorySize, SMEM_BYTES);
    gatr_fused_kernel<<<152, NTHR, SMEM_BYTES>>>(x, ref, w_bil, b_bil, w_out, b_out,
                                                 out, ngroups);
}